// round 7
// baseline (speedup 1.0000x reference)
#include <cuda_runtime.h>
#include <cuda_bf16.h>
#include <cstdint>

#define BB 8
#define CC 64
#define CQ 8
#define NN 4096
#define KT 64
#define NTILES (NN / KT)
#define LOG2E 1.4426950408889634f

// Device scratch (allocation-free rule)
__device__ float g_Q[BB * NN * CQ];            // [b][n][cq] f32, pre-scaled by log2e
__device__ uint4 g_Khi[BB * NN];               // [b][n]: 8 bf16 (hi split)
__device__ uint4 g_Klo[BB * NN];               // [b][n]: 8 bf16 (lo split)
__device__ __nv_bfloat16 g_Vb[BB * CC * NN];   // [b][c][n] bf16 (V^T)

// ---------------------------------------------------------------------------
// PTX helpers (baseline compute_103-safe)
// ---------------------------------------------------------------------------
__device__ __forceinline__ uint32_t smem_u32(const void* p) {
    uint32_t a;
    asm("{ .reg .u64 t; cvta.to.shared.u64 t, %1; cvt.u32.u64 %0, t; }" : "=r"(a) : "l"(p));
    return a;
}
__device__ __forceinline__ uint32_t packbf(float lo, float hi) {
    uint32_t r;
    asm("cvt.rn.bf16x2.f32 %0, %1, %2;" : "=r"(r) : "f"(hi), "f"(lo));
    return r;
}
__device__ __forceinline__ float ex2f(float x) {
    float y;
    asm("ex2.approx.f32 %0, %1;" : "=f"(y) : "f"(x));
    return y;
}
#define LDSM4(r0, r1, r2, r3, a) \
    asm volatile("ldmatrix.sync.aligned.m8n8.x4.shared.b16 {%0,%1,%2,%3}, [%4];" \
        : "=r"(r0), "=r"(r1), "=r"(r2), "=r"(r3) : "r"(a))

#define CP_ASYNC16(dst, src) \
    asm volatile("cp.async.ca.shared.global [%0], [%1], 16;" :: "r"(dst), "l"(src) : "memory")
#define CP_COMMIT() asm volatile("cp.async.commit_group;" ::: "memory")
#define CP_WAIT2()  asm volatile("cp.async.wait_group 2;" ::: "memory")
#define CP_WAIT4()  asm volatile("cp.async.wait_group 4;" ::: "memory")

#define MMA1688(d, a0, a1, b0) \
    asm volatile("mma.sync.aligned.m16n8k8.row.col.f32.bf16.bf16.f32 " \
        "{%0,%1,%2,%3}, {%4,%5}, {%6}, {%0,%1,%2,%3};" \
        : "+f"((d)[0]), "+f"((d)[1]), "+f"((d)[2]), "+f"((d)[3]) \
        : "r"(a0), "r"(a1), "r"(b0))
#define MMA16816_Z(d, a0, a1, a2, a3, b0, b1) \
    asm volatile("mma.sync.aligned.m16n8k16.row.col.f32.bf16.bf16.f32 " \
        "{%0,%1,%2,%3}, {%4,%5,%6,%7}, {%8,%9}, {%10,%10,%10,%10};" \
        : "=f"((d)[0]), "=f"((d)[1]), "=f"((d)[2]), "=f"((d)[3]) \
        : "r"(a0), "r"(a1), "r"(a2), "r"(a3), "r"(b0), "r"(b1), "f"(0.f))
#define MMA16816(d, a0, a1, a2, a3, b0, b1) \
    asm volatile("mma.sync.aligned.m16n8k16.row.col.f32.bf16.bf16.f32 " \
        "{%0,%1,%2,%3}, {%4,%5,%6,%7}, {%8,%9}, {%0,%1,%2,%3};" \
        : "+f"((d)[0]), "+f"((d)[1]), "+f"((d)[2]), "+f"((d)[3]) \
        : "r"(a0), "r"(a1), "r"(a2), "r"(a3), "r"(b0), "r"(b1))

// ---------------------------------------------------------------------------
// Kernel 1: projections, half-split. 128 thr = 64 pixels x 2 channel-halves.
// grid (NN/64, B) = (64, 8) = 512 CTAs -> ~14 warps/SM resident.
// half 0: V channels 0-31 + Q;  half 1: V channels 32-63 + K(hi/lo).
// ---------------------------------------------------------------------------
__global__ void __launch_bounds__(128, 4) proj_kernel(
    const float* __restrict__ x,
    const float* __restrict__ wq, const float* __restrict__ bq,
    const float* __restrict__ wk, const float* __restrict__ bk,
    const float* __restrict__ wv, const float* __restrict__ bv)
{
    __shared__ float wv2[CC * 64];   // [cin][col], per-half rotated (16 KB)
    __shared__ float wqT[CC * CQ];
    __shared__ float wkT[CC * CQ];
    __shared__ float s_bv[CC];
    __shared__ float s_bq[CQ];
    __shared__ float s_bk[CQ];

    const int tid  = threadIdx.x;
    const int half = tid >> 6;
    const int px   = tid & 63;
    const int b    = blockIdx.y;
    const int n    = blockIdx.x * 64 + px;

    // wv staged [cin][col]; within each half-32 rotate by 4*(cin&7) floats
    for (int idx = tid; idx < CC * CC; idx += 128) {
        const int cout = idx >> 6, cin = idx & 63;
        const int col = (cout & 32) + (((cout & 31) + ((cin & 7) << 2)) & 31);
        wv2[cin * 64 + col] = wv[idx];
    }
    for (int idx = tid; idx < CQ * CC; idx += 128) {
        const int cq = idx & 7, cin = idx >> 3;
        wqT[idx] = wq[cq * CC + cin];
        wkT[idx] = wk[cq * CC + cin];
    }
    if (tid < CC) s_bv[tid] = bv[tid];
    if (tid < CQ) { s_bq[tid] = bq[tid]; s_bk[tid] = bk[tid]; }
    __syncthreads();

    const float* xb  = x + (size_t)b * CC * NN + n;
    const float* wqk = half ? wkT : wqT;
    const int    c0  = half * 32;

    float4 accv[8];
    float  accqk[8];
    #pragma unroll
    for (int g = 0; g < 8; ++g) {
        accv[g].x = s_bv[c0 + g * 4 + 0];
        accv[g].y = s_bv[c0 + g * 4 + 1];
        accv[g].z = s_bv[c0 + g * 4 + 2];
        accv[g].w = s_bv[c0 + g * 4 + 3];
    }
    #pragma unroll
    for (int e = 0; e < 8; ++e) accqk[e] = half ? s_bk[e] : s_bq[e];

    #pragma unroll 8
    for (int cp = 0; cp < CC; ++cp) {
        const float xv = xb[(size_t)cp * NN];
        const float4* wr = (const float4*)(wv2 + cp * 64 + c0);
        const int rot = cp & 7;
        #pragma unroll
        for (int g = 0; g < 8; ++g) {
            const float4 w = wr[(g + rot) & 7];       // uniform broadcast
            accv[g].x += w.x * xv;
            accv[g].y += w.y * xv;
            accv[g].z += w.z * xv;
            accv[g].w += w.w * xv;
        }
        const float4 w0 = ((const float4*)(wqk + cp * 8))[0];
        const float4 w1 = ((const float4*)(wqk + cp * 8))[1];
        accqk[0] += w0.x * xv; accqk[1] += w0.y * xv;
        accqk[2] += w0.z * xv; accqk[3] += w0.w * xv;
        accqk[4] += w1.x * xv; accqk[5] += w1.y * xv;
        accqk[6] += w1.z * xv; accqk[7] += w1.w * xv;
    }

    if (half == 0) {
        // Q f32 scaled by log2e
        float4* Qo = (float4*)(g_Q + ((size_t)b * NN + n) * CQ);
        Qo[0] = make_float4(accqk[0] * LOG2E, accqk[1] * LOG2E,
                            accqk[2] * LOG2E, accqk[3] * LOG2E);
        Qo[1] = make_float4(accqk[4] * LOG2E, accqk[5] * LOG2E,
                            accqk[6] * LOG2E, accqk[7] * LOG2E);
    } else {
        // K bf16 hi/lo split
        uint32_t hiw[4], low[4];
        #pragma unroll
        for (int p = 0; p < 4; ++p) {
            const float k0 = accqk[2 * p], k1 = accqk[2 * p + 1];
            const uint32_t h = packbf(k0, k1);
            hiw[p] = h;
            low[p] = packbf(k0 - __uint_as_float(h << 16),
                            k1 - __uint_as_float(h & 0xFFFF0000u));
        }
        g_Khi[(size_t)b * NN + n] = make_uint4(hiw[0], hiw[1], hiw[2], hiw[3]);
        g_Klo[(size_t)b * NN + n] = make_uint4(low[0], low[1], low[2], low[3]);
    }

    // V^T bf16, this half's 32 channels (coalesced 2B rows)
    __nv_bfloat16* Vo = g_Vb + (size_t)b * CC * NN + (size_t)c0 * NN + n;
    #pragma unroll
    for (int g = 0; g < 8; ++g) {
        Vo[(size_t)(g * 4 + 0) * NN] = __float2bfloat16(accv[g].x);
        Vo[(size_t)(g * 4 + 1) * NN] = __float2bfloat16(accv[g].y);
        Vo[(size_t)(g * 4 + 2) * NN] = __float2bfloat16(accv[g].z);
        Vo[(size_t)(g * 4 + 3) * NN] = __float2bfloat16(accv[g].w);
    }
}

// ---------------------------------------------------------------------------
// Attention helpers: half-tile score (2 kt) and half-tile PV.
// ---------------------------------------------------------------------------
__device__ __forceinline__ void score_half(
    uint32_t aKhi_s, uint32_t aKlo_s,
    uint32_t qhi0, uint32_t qhi1, uint32_t qlo0, uint32_t qlo1,
    float& lsum0, float& lsum1, uint32_t A[8])
{
    uint32_t kh[4], kl[4];
    LDSM4(kh[0], kh[1], kh[2], kh[3], aKhi_s);
    LDSM4(kl[0], kl[1], kl[2], kl[3], aKlo_s);
    #pragma unroll
    for (int j = 0; j < 2; ++j) {
        float p0[4], p1[4];
        MMA16816_Z(p0, qhi0, qhi1, qlo0, qlo1, kh[2 * j], kh[2 * j]);
        MMA1688(p0, qhi0, qhi1, kl[2 * j]);
        MMA16816_Z(p1, qhi0, qhi1, qlo0, qlo1, kh[2 * j + 1], kh[2 * j + 1]);
        MMA1688(p1, qhi0, qhi1, kl[2 * j + 1]);
        #pragma unroll
        for (int e = 0; e < 4; ++e) { p0[e] = ex2f(p0[e]); p1[e] = ex2f(p1[e]); }
        lsum0 += (p0[0] + p0[1]) + (p1[0] + p1[1]);
        lsum1 += (p0[2] + p0[3]) + (p1[2] + p1[3]);
        A[4 * j + 0] = packbf(p0[0], p0[1]);
        A[4 * j + 1] = packbf(p0[2], p0[3]);
        A[4 * j + 2] = packbf(p1[0], p1[1]);
        A[4 * j + 3] = packbf(p1[2], p1[3]);
    }
}

__device__ __forceinline__ void pv_half(
    uint32_t vaddr, int ktbase, int m01, int mrow,
    const uint32_t A[8], float acc[8][4])
{
    #pragma unroll
    for (int j = 0; j < 2; ++j) {
        const int kt = ktbase + j;
        const uint32_t term = ((uint32_t)((2 * kt + m01) ^ mrow)) << 4;
        uint32_t vb[16];
        #pragma unroll
        for (int c = 0; c < 4; ++c)
            LDSM4(vb[4 * c + 0], vb[4 * c + 1], vb[4 * c + 2], vb[4 * c + 3],
                  vaddr + c * 2048 + term);
        #pragma unroll
        for (int nb = 0; nb < 8; ++nb)
            MMA16816(acc[nb], A[4 * j + 0], A[4 * j + 1], A[4 * j + 2], A[4 * j + 3],
                     vb[2 * nb], vb[2 * nb + 1]);
    }
}

// ---------------------------------------------------------------------------
// Kernel 2: tensorized fused attention, half-tile software pipeline.
// smem: Khi 4 stages (4KB) | Klo 4 stages (4KB) | V 3 stages (24KB) = 32KB.
// Per body t: PV(t,h0)||score(t,h1), PV(t,h1)||score(t+1,h0) — score MUFU
// hides under PV tensor issue.
// ---------------------------------------------------------------------------
__global__ void __launch_bounds__(128, 4) attn_kernel(float* __restrict__ out)
{
    __shared__ __align__(16) char smraw[8192 + 3 * 8192];

    const int tid  = threadIdx.x;
    const int lane = tid & 31;
    const int w    = tid >> 5;
    const int g    = lane >> 2;
    const int t4   = lane & 3;
    const int b    = blockIdx.y;
    const int ibase = blockIdx.x * 64 + w * 16;

    const uint32_t smb = smem_u32(smraw);

    // Q fragments, hi/lo bf16 split
    const float* Qb = g_Q + (size_t)b * NN * CQ;
    uint32_t qhi[2], qlo[2];
    #pragma unroll
    for (int r = 0; r < 2; ++r) {
        const float* qp = Qb + (size_t)(ibase + g + r * 8) * CQ + 2 * t4;
        const float q0 = qp[0], q1 = qp[1];
        const uint32_t h = packbf(q0, q1);
        qhi[r] = h;
        qlo[r] = packbf(q0 - __uint_as_float(h << 16),
                        q1 - __uint_as_float(h & 0xFFFF0000u));
    }

    // K staging: threads 0-63 copy hi, 64-127 copy lo (16B per tile)
    const uint4* Ksrc = ((tid < 64) ? g_Khi : g_Klo) + (size_t)b * NN + (tid & 63);
    const uint32_t kdst = smb + ((tid < 64) ? 0u : 4096u) + (uint32_t)(tid & 63) * 16u;

    // V staging: 4 x 16B per tile; r stride: smem +2048, gmem +16*NN*2
    const char* Vgb = (const char*)(g_Vb + (size_t)b * CC * NN);
    const uint32_t voff0 = (uint32_t)(tid >> 3) * (NN * 2) + (uint32_t)(tid & 7) * 16;
    const uint32_t vdst0 = smb + 8192 + (uint32_t)(tid >> 3) * 128
                         + (uint32_t)(((tid & 7) ^ ((tid >> 3) & 7)) << 4);

    // ldmatrix addresses
    const uint32_t aKhi = smb + lane * 16;
    const uint32_t aKlo = smb + 4096 + lane * 16;
    const int mat = lane >> 3, mrow = lane & 7, m01 = mat & 1;
    const uint32_t vbase0 = smb + 8192 + (uint32_t)(((mat >> 1) * 8 + mrow)) * 128;

    // Prologue: commit order K0, V0, K1, V1, K2 (5 groups)
    CP_ASYNC16(kdst + 0 * 1024, Ksrc + 0 * KT);  CP_COMMIT();
    #pragma unroll
    for (int r = 0; r < 4; ++r)
        CP_ASYNC16(vdst0 + r * 2048 + 0 * 8192, Vgb + voff0 + r * 131072 + 0 * 128);
    CP_COMMIT();
    CP_ASYNC16(kdst + 1 * 1024, Ksrc + 1 * KT);  CP_COMMIT();
    #pragma unroll
    for (int r = 0; r < 4; ++r)
        CP_ASYNC16(vdst0 + r * 2048 + 1 * 8192, Vgb + voff0 + r * 131072 + 1 * 128);
    CP_COMMIT();
    CP_ASYNC16(kdst + 2 * 1024, Ksrc + 2 * KT);  CP_COMMIT();

    float acc[8][4];
    #pragma unroll
    for (int nb = 0; nb < 8; ++nb)
        #pragma unroll
        for (int e = 0; e < 4; ++e) acc[nb][e] = 0.f;
    float lsum0 = 0.f, lsum1 = 0.f;
    uint32_t A0[8], A1[8];

    CP_WAIT4();            // K0 landed (this thread)
    __syncthreads();       // ...and visible to all
    score_half(aKhi, aKlo, qhi[0], qhi[1], qlo[0], qlo[1], lsum0, lsum1, A0);

    uint32_t vs = 0;       // V stage offset of tile t
    uint32_t vs2 = 16384;  // V stage offset of tile t+2

    #pragma unroll 1
    for (int t = 0; t < NTILES; ++t) {
        CP_WAIT2();        // V(t), K(t+1) landed
        __syncthreads();

        // Prefetch K(t+3), V(t+2) (empty commits keep group arithmetic)
        if (t + 3 < NTILES)
            CP_ASYNC16(kdst + ((uint32_t)(t + 3) & 3u) * 1024u, Ksrc + (size_t)(t + 3) * KT);
        CP_COMMIT();
        if (t + 2 < NTILES) {
            #pragma unroll
            for (int r = 0; r < 4; ++r)
                CP_ASYNC16(vdst0 + r * 2048 + vs2, Vgb + voff0 + r * 131072 + (size_t)(t + 2) * 128);
        }
        CP_COMMIT();

        const uint32_t ks  = ((uint32_t)t & 3u) * 1024u;
        const uint32_t ks1 = ((uint32_t)(t + 1) & 3u) * 1024u;

        // PV(t, h0) || score(t, h1)
        pv_half(vbase0 + vs, 0, m01, mrow, A0, acc);
        score_half(aKhi + ks + 512, aKlo + ks + 512,
                   qhi[0], qhi[1], qlo[0], qlo[1], lsum0, lsum1, A1);
        // PV(t, h1) || score(t+1, h0)
        pv_half(vbase0 + vs, 2, m01, mrow, A1, acc);
        if (t + 1 < NTILES)
            score_half(aKhi + ks1, aKlo + ks1,
                       qhi[0], qhi[1], qlo[0], qlo[1], lsum0, lsum1, A0);

        vs += 8192;  if (vs == 24576)  vs = 0;
        vs2 += 8192; if (vs2 == 24576) vs2 = 0;
    }

    // l: reduce over the 4 lanes of each quad
    lsum0 += __shfl_xor_sync(0xFFFFFFFFu, lsum0, 1);
    lsum0 += __shfl_xor_sync(0xFFFFFFFFu, lsum0, 2);
    lsum1 += __shfl_xor_sync(0xFFFFFFFFu, lsum1, 1);
    lsum1 += __shfl_xor_sync(0xFFFFFFFFu, lsum1, 2);
    const float invA = 1.f / lsum0;
    const float invB = 1.f / lsum1;

    float* outb = out + (size_t)b * CC * NN;
    const int rA = ibase + g;
    const int rB = rA + 8;
    #pragma unroll
    for (int nb = 0; nb < 8; ++nb) {
        const int c = nb * 8 + 2 * t4;
        outb[(size_t)c * NN + rA]       = acc[nb][0] * invA;
        outb[(size_t)(c + 1) * NN + rA] = acc[nb][1] * invA;
        outb[(size_t)c * NN + rB]       = acc[nb][2] * invB;
        outb[(size_t)(c + 1) * NN + rB] = acc[nb][3] * invB;
    }
}

// ---------------------------------------------------------------------------
extern "C" void kernel_launch(void* const* d_in, const int* in_sizes, int n_in,
                              void* d_out, int out_size)
{
    const float* x  = (const float*)d_in[0];
    const float* wq = (const float*)d_in[1];
    const float* bq = (const float*)d_in[2];
    const float* wk = (const float*)d_in[3];
    const float* bk = (const float*)d_in[4];
    const float* wv = (const float*)d_in[5];
    const float* bv = (const float*)d_in[6];
    float* out = (float*)d_out;

    dim3 pgrid(NN / 64, BB);
    proj_kernel<<<pgrid, 128>>>(x, wq, bq, wk, bk, wv, bv);

    dim3 agrid(NN / 64, BB);
    attn_kernel<<<agrid, 128>>>(out);
}

// round 8
// speedup vs baseline: 1.1390x; 1.1390x over previous
#include <cuda_runtime.h>
#include <cuda_bf16.h>
#include <cstdint>

#define BB 8
#define CC 64
#define CQ 8
#define NN 4096
#define KT 64
#define NTILES (NN / KT)
#define LOG2E 1.4426950408889634f

// Device scratch (allocation-free rule)
__device__ float    g_Q[BB * NN * CQ];          // [b][n][cq] f32, pre-scaled by log2e
__device__ uint32_t g_Kt[BB * NN * CQ];         // [b][n]: 8 tf32, pair-permuted (c,c+4)
__device__ __nv_bfloat16 g_Vb[BB * CC * NN];    // [b][c][n] bf16 (V^T)

// ---------------------------------------------------------------------------
// PTX helpers (baseline compute_103-safe: sm_80-era)
// ---------------------------------------------------------------------------
__device__ __forceinline__ uint32_t smem_u32(const void* p) {
    uint32_t a;
    asm("{ .reg .u64 t; cvta.to.shared.u64 t, %1; cvt.u32.u64 %0, t; }" : "=r"(a) : "l"(p));
    return a;
}
__device__ __forceinline__ uint32_t packbf(float lo, float hi) {
    uint32_t r;
    asm("cvt.rn.bf16x2.f32 %0, %1, %2;" : "=r"(r) : "f"(hi), "f"(lo));
    return r;
}
__device__ __forceinline__ uint32_t tf32c(float f) {
    uint32_t r;
    asm("cvt.rna.tf32.f32 %0, %1;" : "=r"(r) : "f"(f));
    return r;
}
__device__ __forceinline__ float ex2f(float x) {
    float y;
    asm("ex2.approx.f32 %0, %1;" : "=f"(y) : "f"(x));
    return y;
}
#define LDSM4(r0, r1, r2, r3, a) \
    asm volatile("ldmatrix.sync.aligned.m8n8.x4.shared.b16 {%0,%1,%2,%3}, [%4];" \
        : "=r"(r0), "=r"(r1), "=r"(r2), "=r"(r3) : "r"(a))
#define LDS64(r0, r1, a) \
    asm volatile("ld.shared.v2.u32 {%0,%1}, [%2];" : "=r"(r0), "=r"(r1) : "r"(a))

#define CP_ASYNC16(dst, src) \
    asm volatile("cp.async.ca.shared.global [%0], [%1], 16;" :: "r"(dst), "l"(src) : "memory")
#define CP_COMMIT() asm volatile("cp.async.commit_group;" ::: "memory")
#define CP_WAIT1()  asm volatile("cp.async.wait_group 1;" ::: "memory")

// m16n8k8 tf32 MMA, C = 0
#define MMAT32_Z(d, a0, a1, a2, a3, b0, b1) \
    asm volatile("mma.sync.aligned.m16n8k8.row.col.f32.tf32.tf32.f32 " \
        "{%0,%1,%2,%3}, {%4,%5,%6,%7}, {%8,%9}, {%10,%10,%10,%10};" \
        : "=f"((d)[0]), "=f"((d)[1]), "=f"((d)[2]), "=f"((d)[3]) \
        : "r"(a0), "r"(a1), "r"(a2), "r"(a3), "r"(b0), "r"(b1), "f"(0.f))
// m16n8k16 bf16 MMA, accumulate in place
#define MMA16816(d, a0, a1, a2, a3, b0, b1) \
    asm volatile("mma.sync.aligned.m16n8k16.row.col.f32.bf16.bf16.f32 " \
        "{%0,%1,%2,%3}, {%4,%5,%6,%7}, {%8,%9}, {%0,%1,%2,%3};" \
        : "+f"((d)[0]), "+f"((d)[1]), "+f"((d)[2]), "+f"((d)[3]) \
        : "r"(a0), "r"(a1), "r"(a2), "r"(a3), "r"(b0), "r"(b1))

// ---------------------------------------------------------------------------
// Kernel 1: projections, half-split. 128 thr = 64 pixels x 2 channel-halves.
// half 0: V channels 0-31 + Q;  half 1: V channels 32-63 + K (tf32 permuted).
// ---------------------------------------------------------------------------
__global__ void __launch_bounds__(128, 4) proj_kernel(
    const float* __restrict__ x,
    const float* __restrict__ wq, const float* __restrict__ bq,
    const float* __restrict__ wk, const float* __restrict__ bk,
    const float* __restrict__ wv, const float* __restrict__ bv)
{
    __shared__ float wv2[CC * 64];   // [cin][col], per-half rotated (16 KB)
    __shared__ float wqT[CC * CQ];
    __shared__ float wkT[CC * CQ];
    __shared__ float s_bv[CC];
    __shared__ float s_bq[CQ];
    __shared__ float s_bk[CQ];

    const int tid  = threadIdx.x;
    const int half = tid >> 6;
    const int px   = tid & 63;
    const int b    = blockIdx.y;
    const int n    = blockIdx.x * 64 + px;

    for (int idx = tid; idx < CC * CC; idx += 128) {
        const int cout = idx >> 6, cin = idx & 63;
        const int col = (cout & 32) + (((cout & 31) + ((cin & 7) << 2)) & 31);
        wv2[cin * 64 + col] = wv[idx];
    }
    for (int idx = tid; idx < CQ * CC; idx += 128) {
        const int cq = idx & 7, cin = idx >> 3;
        wqT[idx] = wq[cq * CC + cin];
        wkT[idx] = wk[cq * CC + cin];
    }
    if (tid < CC) s_bv[tid] = bv[tid];
    if (tid < CQ) { s_bq[tid] = bq[tid]; s_bk[tid] = bk[tid]; }
    __syncthreads();

    const float* xb  = x + (size_t)b * CC * NN + n;
    const float* wqk = half ? wkT : wqT;
    const int    c0  = half * 32;

    float4 accv[8];
    float  accqk[8];
    #pragma unroll
    for (int g = 0; g < 8; ++g) {
        accv[g].x = s_bv[c0 + g * 4 + 0];
        accv[g].y = s_bv[c0 + g * 4 + 1];
        accv[g].z = s_bv[c0 + g * 4 + 2];
        accv[g].w = s_bv[c0 + g * 4 + 3];
    }
    #pragma unroll
    for (int e = 0; e < 8; ++e) accqk[e] = half ? s_bk[e] : s_bq[e];

    #pragma unroll 8
    for (int cp = 0; cp < CC; ++cp) {
        const float xv = xb[(size_t)cp * NN];
        const float4* wr = (const float4*)(wv2 + cp * 64 + c0);
        const int rot = cp & 7;
        #pragma unroll
        for (int g = 0; g < 8; ++g) {
            const float4 w = wr[(g + rot) & 7];       // uniform broadcast
            accv[g].x += w.x * xv;
            accv[g].y += w.y * xv;
            accv[g].z += w.z * xv;
            accv[g].w += w.w * xv;
        }
        const float4 w0 = ((const float4*)(wqk + cp * 8))[0];
        const float4 w1 = ((const float4*)(wqk + cp * 8))[1];
        accqk[0] += w0.x * xv; accqk[1] += w0.y * xv;
        accqk[2] += w0.z * xv; accqk[3] += w0.w * xv;
        accqk[4] += w1.x * xv; accqk[5] += w1.y * xv;
        accqk[6] += w1.z * xv; accqk[7] += w1.w * xv;
    }

    if (half == 0) {
        float4* Qo = (float4*)(g_Q + ((size_t)b * NN + n) * CQ);
        Qo[0] = make_float4(accqk[0] * LOG2E, accqk[1] * LOG2E,
                            accqk[2] * LOG2E, accqk[3] * LOG2E);
        Qo[1] = make_float4(accqk[4] * LOG2E, accqk[5] * LOG2E,
                            accqk[6] * LOG2E, accqk[7] * LOG2E);
    } else {
        // K tf32, pair-permuted: [(k0,k4),(k1,k5),(k2,k6),(k3,k7)]
        uint4* Ko = (uint4*)(g_Kt + ((size_t)b * NN + n) * CQ);
        Ko[0] = make_uint4(tf32c(accqk[0]), tf32c(accqk[4]),
                           tf32c(accqk[1]), tf32c(accqk[5]));
        Ko[1] = make_uint4(tf32c(accqk[2]), tf32c(accqk[6]),
                           tf32c(accqk[3]), tf32c(accqk[7]));
    }

    __nv_bfloat16* Vo = g_Vb + (size_t)b * CC * NN + (size_t)c0 * NN + n;
    #pragma unroll
    for (int g = 0; g < 8; ++g) {
        Vo[(size_t)(g * 4 + 0) * NN] = __float2bfloat16(accv[g].x);
        Vo[(size_t)(g * 4 + 1) * NN] = __float2bfloat16(accv[g].y);
        Vo[(size_t)(g * 4 + 2) * NN] = __float2bfloat16(accv[g].z);
        Vo[(size_t)(g * 4 + 3) * NN] = __float2bfloat16(accv[g].w);
    }
}

// ---------------------------------------------------------------------------
// Kernel 2: tensorized fused attention (round-6 skeleton, tf32 scores).
// Block = 128 thr = 4 warps x 16 query rows. grid (64, 8) = 512 CTAs.
// smem: K 3 stages x 2KB (6KB) | V 3 stages x 8KB (24KB) = 30 KB.
// ---------------------------------------------------------------------------
__global__ void __launch_bounds__(128, 4) attn_kernel(float* __restrict__ out)
{
    __shared__ __align__(16) char smraw[6144 + 3 * 8192];

    const int tid  = threadIdx.x;
    const int lane = tid & 31;
    const int w    = tid >> 5;
    const int g    = lane >> 2;
    const int t4   = lane & 3;
    const int b    = blockIdx.y;
    const int ibase = blockIdx.x * 64 + w * 16;

    const uint32_t smb = smem_u32(smraw);

    // Q A-fragment (m16n8k8 tf32): a0=(g,t4) a1=(g+8,t4) a2=(g,t4+4) a3=(g+8,t4+4)
    const float* Qb = g_Q + (size_t)b * NN * CQ;
    const float* q0p = Qb + (size_t)(ibase + g) * CQ;
    const float* q1p = Qb + (size_t)(ibase + g + 8) * CQ;
    const uint32_t qa0 = tf32c(q0p[t4]);
    const uint32_t qa1 = tf32c(q1p[t4]);
    const uint32_t qa2 = tf32c(q0p[t4 + 4]);
    const uint32_t qa3 = tf32c(q1p[t4 + 4]);

    // K staging: 128 threads x 16B = 2KB/tile (thread = half a key)
    const uint32_t* Ksrc = g_Kt + (size_t)b * NN * CQ + (size_t)(tid >> 1) * 8 + (tid & 1) * 4;
    const uint32_t kdst = smb + (uint32_t)(tid >> 1) * 32 + (uint32_t)(tid & 1) * 16;

    // V staging: 4 x 16B per tile, xor-swizzled rows (V region at +6144)
    const char* Vgb = (const char*)(g_Vb + (size_t)b * CC * NN);
    const uint32_t voff0 = (uint32_t)(tid >> 3) * (NN * 2) + (uint32_t)(tid & 7) * 16;
    const uint32_t vdst0 = smb + 6144 + (uint32_t)(tid >> 3) * 128
                         + (uint32_t)(((tid & 7) ^ ((tid >> 3) & 7)) << 4);

    // Score B-fragment LDS address: key = lane>>2 within n-tile, chans (t4, t4+4)
    const uint32_t kfrag0 = smb + (uint32_t)(lane >> 2) * 32 + (uint32_t)t4 * 8;

    // V ldmatrix addresses
    const int mat = lane >> 3, mrow = lane & 7, m01 = mat & 1;
    const uint32_t vbase0 = smb + 6144 + (uint32_t)((mat >> 1) * 8 + mrow) * 128;

    // Prologue: tiles 0, 1 (one commit group per tile: K then V)
    #pragma unroll
    for (int t = 0; t < 2; ++t) {
        CP_ASYNC16(kdst + t * 2048, Ksrc + (size_t)t * KT * CQ);
        #pragma unroll
        for (int r = 0; r < 4; ++r)
            CP_ASYNC16(vdst0 + r * 2048 + t * 8192, Vgb + voff0 + r * 131072 + t * 128);
        CP_COMMIT();
    }

    float acc[8][4];
    #pragma unroll
    for (int nb = 0; nb < 8; ++nb)
        #pragma unroll
        for (int e = 0; e < 4; ++e) acc[nb][e] = 0.f;
    float lsum0 = 0.f, lsum1 = 0.f;
    uint32_t ksoff = 0, vsoff = 0;

    #pragma unroll 1
    for (int t = 0; t < NTILES; ++t) {
        CP_WAIT1();             // tile t landed
        __syncthreads();        // ...visible to all; stage t-1 fully consumed

        // Prefetch tile t+2 into stage (t+2)%3
        {
            const int tc = t + 2;
            uint32_t ks2 = ksoff + 4096;  if (ks2 >= 6144)  ks2 -= 6144;
            uint32_t vs2 = vsoff + 16384; if (vs2 >= 24576) vs2 -= 24576;
            if (tc < NTILES) {
                CP_ASYNC16(kdst + ks2, Ksrc + (size_t)tc * KT * CQ);
                #pragma unroll
                for (int r = 0; r < 4; ++r)
                    CP_ASYNC16(vdst0 + r * 2048 + vs2,
                               Vgb + voff0 + r * 131072 + (size_t)tc * 128);
            }
            CP_COMMIT();        // always commit to keep group arithmetic
        }

        #pragma unroll
        for (int kt = 0; kt < 4; ++kt) {
            // scores for n-tiles 2kt, 2kt+1 (8 keys each): 1 tf32 MMA each
            uint32_t b00, b01, b10, b11;
            LDS64(b00, b01, kfrag0 + ksoff + (uint32_t)(2 * kt) * 256);
            LDS64(b10, b11, kfrag0 + ksoff + (uint32_t)(2 * kt) * 256 + 256);
            float p0[4], p1[4];
            MMAT32_Z(p0, qa0, qa1, qa2, qa3, b00, b01);
            MMAT32_Z(p1, qa0, qa1, qa2, qa3, b10, b11);

            #pragma unroll
            for (int e = 0; e < 4; ++e) { p0[e] = ex2f(p0[e]); p1[e] = ex2f(p1[e]); }
            lsum0 += (p0[0] + p0[1]) + (p1[0] + p1[1]);
            lsum1 += (p0[2] + p0[3]) + (p1[2] + p1[3]);

            const uint32_t a0 = packbf(p0[0], p0[1]);
            const uint32_t a1 = packbf(p0[2], p0[3]);
            const uint32_t a2 = packbf(p1[0], p1[1]);
            const uint32_t a3 = packbf(p1[2], p1[3]);

            const uint32_t term = ((uint32_t)((2 * kt + m01) ^ mrow)) << 4;
            uint32_t vb[16];
            #pragma unroll
            for (int c = 0; c < 4; ++c)
                LDSM4(vb[4 * c + 0], vb[4 * c + 1], vb[4 * c + 2], vb[4 * c + 3],
                      vbase0 + vsoff + c * 2048 + term);
            #pragma unroll
            for (int nb = 0; nb < 8; ++nb)
                MMA16816(acc[nb], a0, a1, a2, a3, vb[2 * nb], vb[2 * nb + 1]);
        }

        ksoff += 2048; if (ksoff == 6144)  ksoff = 0;
        vsoff += 8192; if (vsoff == 24576) vsoff = 0;
    }

    // l: reduce over the 4 lanes of each quad
    lsum0 += __shfl_xor_sync(0xFFFFFFFFu, lsum0, 1);
    lsum0 += __shfl_xor_sync(0xFFFFFFFFu, lsum0, 2);
    lsum1 += __shfl_xor_sync(0xFFFFFFFFu, lsum1, 1);
    lsum1 += __shfl_xor_sync(0xFFFFFFFFu, lsum1, 2);
    const float invA = 1.f / lsum0;
    const float invB = 1.f / lsum1;

    float* outb = out + (size_t)b * CC * NN;
    const int rA = ibase + g;
    const int rB = rA + 8;
    #pragma unroll
    for (int nb = 0; nb < 8; ++nb) {
        const int c = nb * 8 + 2 * t4;
        outb[(size_t)c * NN + rA]       = acc[nb][0] * invA;
        outb[(size_t)(c + 1) * NN + rA] = acc[nb][1] * invA;
        outb[(size_t)c * NN + rB]       = acc[nb][2] * invB;
        outb[(size_t)(c + 1) * NN + rB] = acc[nb][3] * invB;
    }
}

// ---------------------------------------------------------------------------
extern "C" void kernel_launch(void* const* d_in, const int* in_sizes, int n_in,
                              void* d_out, int out_size)
{
    const float* x  = (const float*)d_in[0];
    const float* wq = (const float*)d_in[1];
    const float* bq = (const float*)d_in[2];
    const float* wk = (const float*)d_in[3];
    const float* bk = (const float*)d_in[4];
    const float* wv = (const float*)d_in[5];
    const float* bv = (const float*)d_in[6];
    float* out = (float*)d_out;

    dim3 pgrid(NN / 64, BB);
    proj_kernel<<<pgrid, 128>>>(x, wq, bq, wk, bk, wv, bv);

    dim3 agrid(NN / 64, BB);
    attn_kernel<<<agrid, 128>>>(out);
}